// round 1
// baseline (speedup 1.0000x reference)
#include <cuda_runtime.h>
#include <cstdint>

#define TOK      1024
#define HIDDEN   4096
#define NQH      32
#define NKVH     8
#define HD       128
#define QKV_N    6144
#define TOTAL_KV 3072
#define CACHE_LEN 8192

// ---------------- scratch (static device globals; allocation-free) ----------------
__device__ float g_xqkv[TOK * QKV_N];            // 25 MB
__device__ float g_keys[TOTAL_KV * NKVH * HD];   // 12.6 MB
__device__ float g_vals[TOTAL_KV * NKVH * HD];
__device__ float g_attn[TOK * HIDDEN];           // 16.8 MB

// ---------------- tf32 helpers ----------------
__device__ __forceinline__ uint32_t f2tf(float x) {
    uint32_t r;
    asm("cvt.rna.tf32.f32 %0, %1;" : "=r"(r) : "f"(x));
    return r;
}
__device__ __forceinline__ float tfbits(float x) { return __uint_as_float(f2tf(x)); }
__device__ __forceinline__ float4 cvt4(float4 v) {
    float4 r;
    r.x = tfbits(v.x); r.y = tfbits(v.y); r.z = tfbits(v.z); r.w = tfbits(v.w);
    return r;
}

// D += A(16x8,row) * B(8x8,col)  tf32
__device__ __forceinline__ void mma_tf32(float* d, const uint32_t* a, const uint32_t* b) {
    asm volatile(
        "mma.sync.aligned.m16n8k8.row.col.f32.tf32.tf32.f32 "
        "{%0,%1,%2,%3}, {%4,%5,%6,%7}, {%8,%9}, {%0,%1,%2,%3};\n"
        : "+f"(d[0]), "+f"(d[1]), "+f"(d[2]), "+f"(d[3])
        : "r"(a[0]), "r"(a[1]), "r"(a[2]), "r"(a[3]), "r"(b[0]), "r"(b[1]));
}

// ---------------- generic tf32 GEMM: C[M,N] = A[M,K] @ B[K,N] ----------------
// BM=128, BN=128, BK=16. 256 threads = 8 warps (2m x 4n), warp tile 64x32.
__global__ __launch_bounds__(256) void gemm_tf32(const float* __restrict__ A,
                                                 const float* __restrict__ B,
                                                 float* __restrict__ C,
                                                 int M, int N, int K) {
    __shared__ float As[128][20];   // pad 16->20: conflict-free frag reads, f4-aligned
    __shared__ float Bs[16][132];

    const int tid  = threadIdx.x;
    const int warp = tid >> 5, lane = tid & 31;
    const int wm = warp >> 2, wn = warp & 3;
    const int g = lane >> 2, t4 = lane & 3;
    const int bm = blockIdx.y * 128, bn = blockIdx.x * 128;

    // global->smem mapping
    const int ar = tid >> 2, ac = (tid & 3) * 4;   // rows ar, ar+64 ; 16-col tile
    const int br = tid >> 5, bc = (tid & 31) * 4;  // rows br, br+8  ; 128-col tile

    float4 pa0 = *(const float4*)(A + (size_t)(bm + ar) * K + ac);
    float4 pa1 = *(const float4*)(A + (size_t)(bm + ar + 64) * K + ac);
    float4 pb0 = *(const float4*)(B + (size_t)br * N + bn + bc);
    float4 pb1 = *(const float4*)(B + (size_t)(br + 8) * N + bn + bc);

    float acc[4][4][4];
#pragma unroll
    for (int i = 0; i < 4; i++)
#pragma unroll
        for (int j = 0; j < 4; j++)
#pragma unroll
            for (int e = 0; e < 4; e++) acc[i][j][e] = 0.f;

    for (int k0 = 0; k0 < K; k0 += 16) {
        *(float4*)&As[ar][ac]      = cvt4(pa0);
        *(float4*)&As[ar + 64][ac] = cvt4(pa1);
        *(float4*)&Bs[br][bc]      = cvt4(pb0);
        *(float4*)&Bs[br + 8][bc]  = cvt4(pb1);
        __syncthreads();

        int kn = k0 + 16;
        if (kn < K) {
            pa0 = *(const float4*)(A + (size_t)(bm + ar) * K + kn + ac);
            pa1 = *(const float4*)(A + (size_t)(bm + ar + 64) * K + kn + ac);
            pb0 = *(const float4*)(B + (size_t)(kn + br) * N + bn + bc);
            pb1 = *(const float4*)(B + (size_t)(kn + br + 8) * N + bn + bc);
        }

#pragma unroll
        for (int kk = 0; kk < 16; kk += 8) {
            uint32_t af[4][4], bf[4][2];
#pragma unroll
            for (int mt = 0; mt < 4; mt++) {
                int r = wm * 64 + mt * 16;
                af[mt][0] = __float_as_uint(As[r + g][kk + t4]);
                af[mt][1] = __float_as_uint(As[r + g + 8][kk + t4]);
                af[mt][2] = __float_as_uint(As[r + g][kk + t4 + 4]);
                af[mt][3] = __float_as_uint(As[r + g + 8][kk + t4 + 4]);
            }
#pragma unroll
            for (int nt = 0; nt < 4; nt++) {
                int c = wn * 32 + nt * 8 + g;
                bf[nt][0] = __float_as_uint(Bs[kk + t4][c]);
                bf[nt][1] = __float_as_uint(Bs[kk + t4 + 4][c]);
            }
#pragma unroll
            for (int mt = 0; mt < 4; mt++)
#pragma unroll
                for (int nt = 0; nt < 4; nt++) mma_tf32(acc[mt][nt], af[mt], bf[nt]);
        }
        __syncthreads();
    }

#pragma unroll
    for (int mt = 0; mt < 4; mt++) {
        int r0 = bm + wm * 64 + mt * 16 + g;
#pragma unroll
        for (int nt = 0; nt < 4; nt++) {
            int c0 = bn + wn * 32 + nt * 8 + 2 * t4;
            *(float2*)&C[(size_t)r0 * N + c0]       = make_float2(acc[mt][nt][0], acc[mt][nt][1]);
            *(float2*)&C[(size_t)(r0 + 8) * N + c0] = make_float2(acc[mt][nt][2], acc[mt][nt][3]);
        }
    }
}

// ---------------- RoPE (in place on q + k heads of g_xqkv) ----------------
__global__ void rope_kernel(const int* __restrict__ seqstarts, const int* __restrict__ start_pos) {
    __shared__ float invf[64];
    int t = blockIdx.x;
    if (threadIdx.x < 64)
        invf[threadIdx.x] = powf(10000.0f, -(float)threadIdx.x / 64.0f);
    __syncthreads();
    int b = 0;
#pragma unroll
    for (int i = 1; i < 4; i++)
        if (t >= seqstarts[i]) b = i;
    float pos = (float)(t - seqstarts[b] + start_pos[b]);
    for (int w = threadIdx.x; w < (NQH + NKVH) * 64; w += blockDim.x) {
        int hh = w >> 6, i = w & 63;
        float ang = pos * invf[i];
        float s, c;
        sincosf(ang, &s, &c);
        float* p = g_xqkv + (size_t)t * QKV_N + hh * HD + 2 * i;
        float x1 = p[0], x2 = p[1];
        p[0] = x1 * c - x2 * s;
        p[1] = x1 * s + x2 * c;
    }
}

// ---------------- gather/merge KV into contiguous [TOTAL_KV, NKVH, HD] ----------------
__global__ void gather_kv(const float* __restrict__ kv_cache,
                          const int* __restrict__ seqstarts, const int* __restrict__ kvstarts,
                          const int* __restrict__ cachestarts, const int* __restrict__ start_pos) {
    int kk = blockIdx.x;   // kv row
    int h  = blockIdx.y;   // kv head
    int d  = threadIdx.x;  // dim
    int b = 0;
#pragma unroll
    for (int i = 1; i < 4; i++)
        if (kk >= kvstarts[i]) b = i;
    int pkv = kk - kvstarts[b];
    float kvv, vvv;
    if (pkv >= start_pos[b]) {
        int t = seqstarts[b] + pkv - start_pos[b];
        kvv = g_xqkv[(size_t)t * QKV_N + (NQH + h) * HD + d];
        vvv = g_xqkv[(size_t)t * QKV_N + (NQH + NKVH + h) * HD + d];
    } else {
        size_t cidx = (size_t)cachestarts[b] + pkv;
        kvv = kv_cache[(cidx * NKVH + h) * HD + d];
        vvv = kv_cache[(size_t)CACHE_LEN * NKVH * HD + (cidx * NKVH + h) * HD + d];
    }
    g_keys[((size_t)kk * NKVH + h) * HD + d] = kvv;
    g_vals[((size_t)kk * NKVH + h) * HD + d] = vvv;
}

// ---------------- flash attention: BQ=64, KV chunks of 64, tf32 mma ----------------
// grid (16 qtiles, 32 heads), 128 threads (4 warps, each owns 16 q rows)
__global__ __launch_bounds__(128) void attn_kernel(const int* __restrict__ seqstarts,
                                                   const int* __restrict__ kvstarts,
                                                   const int* __restrict__ start_pos) {
    extern __shared__ float sm[];
    float* Qs = sm;                 // [64][132]
    float* Ks = sm + 64 * 132;      // [64][132]
    float* Vs = sm + 2 * 64 * 132;  // [64][132]
    float* Ss = sm + 3 * 64 * 132;  // [64][65]

    const int qtile = blockIdx.x, h = blockIdx.y, kvh = h >> 2;
    const int tid = threadIdx.x, warp = tid >> 5, lane = tid & 31;
    const int g = lane >> 2, t4 = lane & 3;
    const int rb = warp * 16;
    const int qbase = qtile * 64;

    int b = 0;
#pragma unroll
    for (int i = 1; i < 4; i++)
        if (qbase >= seqstarts[i]) b = i;
    const int pos0 = qbase - seqstarts[b] + start_pos[b];
    const int kv_lo = kvstarts[b];
    const int nchunk = (pos0 + 64 + 63) >> 6;

    // load Q tile (tf32-converted)
    for (int idx = tid; idx < 64 * 32; idx += 128) {
        int r = idx >> 5, c = (idx & 31) << 2;
        float4 v = *(const float4*)(g_xqkv + (size_t)(qbase + r) * QKV_N + h * HD + c);
        *(float4*)&Qs[r * 132 + c] = cvt4(v);
    }

    float o[16][4];
#pragma unroll
    for (int nt = 0; nt < 16; nt++)
#pragma unroll
        for (int e = 0; e < 4; e++) o[nt][e] = 0.f;
    float m0 = -1e30f, m1 = -1e30f, l0 = 0.f, l1 = 0.f;
    const float scale = 0.08838834764831845f;  // 1/sqrt(128)

    for (int ch = 0; ch < nchunk; ch++) {
        const int kvb = ch * 64;
        __syncthreads();  // protect Ks/Vs reuse (also orders Q writes on first iter)
        for (int idx = tid; idx < 64 * 32; idx += 128) {
            int r = idx >> 5, c = (idx & 31) << 2;
            size_t go = ((size_t)(kv_lo + kvb + r) * NKVH + kvh) * HD + c;
            *(float4*)&Ks[r * 132 + c] = cvt4(*(const float4*)(g_keys + go));
            *(float4*)&Vs[r * 132 + c] = cvt4(*(const float4*)(g_vals + go));
        }
        __syncthreads();

        // S = Q @ K^T  (warp: 16 rows x 64 kv cols)
        float s[8][4];
#pragma unroll
        for (int nt = 0; nt < 8; nt++)
#pragma unroll
            for (int e = 0; e < 4; e++) s[nt][e] = 0.f;
#pragma unroll
        for (int k0 = 0; k0 < 128; k0 += 8) {
            uint32_t a[4];
            a[0] = __float_as_uint(Qs[(rb + g) * 132 + k0 + t4]);
            a[1] = __float_as_uint(Qs[(rb + g + 8) * 132 + k0 + t4]);
            a[2] = __float_as_uint(Qs[(rb + g) * 132 + k0 + t4 + 4]);
            a[3] = __float_as_uint(Qs[(rb + g + 8) * 132 + k0 + t4 + 4]);
#pragma unroll
            for (int nt = 0; nt < 8; nt++) {
                uint32_t bb[2];
                bb[0] = __float_as_uint(Ks[(nt * 8 + g) * 132 + k0 + t4]);
                bb[1] = __float_as_uint(Ks[(nt * 8 + g) * 132 + k0 + t4 + 4]);
                mma_tf32(s[nt], a, bb);
            }
        }

        // mask + online softmax. rows rb+g (regs 0,1) and rb+g+8 (regs 2,3)
        const int plim0 = pos0 + rb + g;
        const int plim1 = plim0 + 8;
        float mx0 = -1e30f, mx1 = -1e30f;
#pragma unroll
        for (int nt = 0; nt < 8; nt++) {
            int c0 = kvb + nt * 8 + 2 * t4;
            float v0 = s[nt][0] * scale; if (c0     > plim0) v0 = -1e30f;
            float v1 = s[nt][1] * scale; if (c0 + 1 > plim0) v1 = -1e30f;
            float v2 = s[nt][2] * scale; if (c0     > plim1) v2 = -1e30f;
            float v3 = s[nt][3] * scale; if (c0 + 1 > plim1) v3 = -1e30f;
            s[nt][0] = v0; s[nt][1] = v1; s[nt][2] = v2; s[nt][3] = v3;
            mx0 = fmaxf(mx0, fmaxf(v0, v1));
            mx1 = fmaxf(mx1, fmaxf(v2, v3));
        }
        mx0 = fmaxf(mx0, __shfl_xor_sync(0xffffffffu, mx0, 1));
        mx0 = fmaxf(mx0, __shfl_xor_sync(0xffffffffu, mx0, 2));
        mx1 = fmaxf(mx1, __shfl_xor_sync(0xffffffffu, mx1, 1));
        mx1 = fmaxf(mx1, __shfl_xor_sync(0xffffffffu, mx1, 2));
        float mn0 = fmaxf(m0, mx0), mn1 = fmaxf(m1, mx1);
        float al0 = __expf(m0 - mn0), al1 = __expf(m1 - mn1);
        float sum0 = 0.f, sum1 = 0.f;
#pragma unroll
        for (int nt = 0; nt < 8; nt++) {
            float p0 = __expf(s[nt][0] - mn0); sum0 += p0;
            float p1 = __expf(s[nt][1] - mn0); sum0 += p1;
            float p2 = __expf(s[nt][2] - mn1); sum1 += p2;
            float p3 = __expf(s[nt][3] - mn1); sum1 += p3;
            int c0 = nt * 8 + 2 * t4;
            Ss[(rb + g) * 65 + c0]         = tfbits(p0);
            Ss[(rb + g) * 65 + c0 + 1]     = tfbits(p1);
            Ss[(rb + g + 8) * 65 + c0]     = tfbits(p2);
            Ss[(rb + g + 8) * 65 + c0 + 1] = tfbits(p3);
        }
        sum0 += __shfl_xor_sync(0xffffffffu, sum0, 1);
        sum0 += __shfl_xor_sync(0xffffffffu, sum0, 2);
        sum1 += __shfl_xor_sync(0xffffffffu, sum1, 1);
        sum1 += __shfl_xor_sync(0xffffffffu, sum1, 2);
        l0 = l0 * al0 + sum0;
        l1 = l1 * al1 + sum1;
        m0 = mn0; m1 = mn1;
#pragma unroll
        for (int nt = 0; nt < 16; nt++) {
            o[nt][0] *= al0; o[nt][1] *= al0;
            o[nt][2] *= al1; o[nt][3] *= al1;
        }
        __syncwarp();

        // O += P @ V  (warp: 16 rows x 128 dims, contract over 64 kv)
#pragma unroll
        for (int k0 = 0; k0 < 64; k0 += 8) {
            uint32_t a[4];
            a[0] = __float_as_uint(Ss[(rb + g) * 65 + k0 + t4]);
            a[1] = __float_as_uint(Ss[(rb + g + 8) * 65 + k0 + t4]);
            a[2] = __float_as_uint(Ss[(rb + g) * 65 + k0 + t4 + 4]);
            a[3] = __float_as_uint(Ss[(rb + g + 8) * 65 + k0 + t4 + 4]);
#pragma unroll
            for (int nt = 0; nt < 16; nt++) {
                uint32_t bb[2];
                bb[0] = __float_as_uint(Vs[(k0 + t4) * 132 + nt * 8 + g]);
                bb[1] = __float_as_uint(Vs[(k0 + t4 + 4) * 132 + nt * 8 + g]);
                mma_tf32(o[nt], a, bb);
            }
        }
        __syncwarp();
    }

    float il0 = 1.f / l0, il1 = 1.f / l1;
#pragma unroll
    for (int nt = 0; nt < 16; nt++) {
        int r0 = qbase + rb + g;
        int c = h * HD + nt * 8 + 2 * t4;
        *(float2*)&g_attn[(size_t)r0 * HIDDEN + c]       = make_float2(o[nt][0] * il0, o[nt][1] * il0);
        *(float2*)&g_attn[(size_t)(r0 + 8) * HIDDEN + c] = make_float2(o[nt][2] * il1, o[nt][3] * il1);
    }
}

// ---------------- launch ----------------
extern "C" void kernel_launch(void* const* d_in, const int* in_sizes, int n_in,
                              void* d_out, int out_size) {
    const float* x           = (const float*)d_in[0];
    const float* wqkv        = (const float*)d_in[1];
    const float* wo          = (const float*)d_in[2];
    const float* kv_cache    = (const float*)d_in[3];
    const int*   seqstarts   = (const int*)d_in[4];
    const int*   kvstarts    = (const int*)d_in[5];
    const int*   cachestarts = (const int*)d_in[6];
    const int*   start_pos   = (const int*)d_in[7];
    float*       out         = (float*)d_out;

    float *p_xqkv, *p_attn;
    cudaGetSymbolAddress((void**)&p_xqkv, g_xqkv);
    cudaGetSymbolAddress((void**)&p_attn, g_attn);

    // 1) xqkv = x @ wqkv
    gemm_tf32<<<dim3(QKV_N / 128, TOK / 128), 256>>>(x, wqkv, p_xqkv, TOK, QKV_N, HIDDEN);
    // 2) RoPE on q,k
    rope_kernel<<<TOK, 256>>>(seqstarts, start_pos);
    // 3) merge new k/v with cache
    gather_kv<<<dim3(TOTAL_KV, NKVH), 128>>>(kv_cache, seqstarts, kvstarts, cachestarts, start_pos);
    // 4) flash attention
    const int smem_bytes = (3 * 64 * 132 + 64 * 65) * (int)sizeof(float);  // ~118 KB
    cudaFuncSetAttribute(attn_kernel, cudaFuncAttributeMaxDynamicSharedMemorySize, smem_bytes);
    attn_kernel<<<dim3(TOK / 64, NQH), 128, smem_bytes>>>(seqstarts, kvstarts, start_pos);
    // 5) out = attn @ wo
    gemm_tf32<<<dim3(HIDDEN / 128, TOK / 128), 256>>>(p_attn, wo, out, TOK, HIDDEN, HIDDEN);
}

// round 2
// speedup vs baseline: 1.1833x; 1.1833x over previous
#include <cuda_runtime.h>
#include <cstdint>

#define TOK      1024
#define HIDDEN   4096
#define NQH      32
#define NKVH     8
#define HD       128
#define QKV_N    6144
#define TOTAL_KV 3072
#define CACHE_LEN 8192

// ---------------- scratch (static device globals; allocation-free) ----------------
__device__ float g_xqkv[TOK * QKV_N];
__device__ float g_keys[TOTAL_KV * NKVH * HD];
__device__ float g_vals[TOTAL_KV * NKVH * HD];
__device__ float g_attn[TOK * HIDDEN];

// ---------------- tf32 helpers ----------------
__device__ __forceinline__ uint32_t f2tf(float x) {
    uint32_t r;
    asm("cvt.rna.tf32.f32 %0, %1;" : "=r"(r) : "f"(x));
    return r;
}
__device__ __forceinline__ float tfbits(float x) { return __uint_as_float(f2tf(x)); }
__device__ __forceinline__ float4 cvt4(float4 v) {
    float4 r;
    r.x = tfbits(v.x); r.y = tfbits(v.y); r.z = tfbits(v.z); r.w = tfbits(v.w);
    return r;
}

// D += A(16x8,row) * B(8x8,col)  tf32
__device__ __forceinline__ void mma_tf32(float* d, const uint32_t* a, const uint32_t* b) {
    asm volatile(
        "mma.sync.aligned.m16n8k8.row.col.f32.tf32.tf32.f32 "
        "{%0,%1,%2,%3}, {%4,%5,%6,%7}, {%8,%9}, {%0,%1,%2,%3};\n"
        : "+f"(d[0]), "+f"(d[1]), "+f"(d[2]), "+f"(d[3])
        : "r"(a[0]), "r"(a[1]), "r"(a[2]), "r"(a[3]), "r"(b[0]), "r"(b[1]));
}

// ---------------- tf32 GEMM: C[M,N] = A[M,K] @ B[K,N] ----------------
// BM=128, BN=128, BK=32. 256 threads = 8 warps (2m x 4n), warp tile 64x32.
// Double-buffered smem, one __syncthreads per k-tile, register prefetch.
#define AS_STRIDE 36
#define BS_STRIDE 132
#define AS_STAGE  (128 * AS_STRIDE)   // 4608 floats
#define BS_STAGE  (32 * BS_STRIDE)    // 4224 floats
#define GEMM_SMEM ((2 * AS_STAGE + 2 * BS_STAGE) * 4)

__global__ __launch_bounds__(256) void gemm_tf32(const float* __restrict__ A,
                                                 const float* __restrict__ B,
                                                 float* __restrict__ C,
                                                 int M, int N, int K) {
    extern __shared__ float sm[];
    float* As = sm;                 // [2][128][36]
    float* Bs = sm + 2 * AS_STAGE;  // [2][32][132]

    const int tid  = threadIdx.x;
    const int warp = tid >> 5, lane = tid & 31;
    const int wm = warp >> 2, wn = warp & 3;
    const int g = lane >> 2, t4 = lane & 3;
    const int bm = blockIdx.y * 128, bn = blockIdx.x * 128;

    // per-thread load slots: 4 float4 of A, 4 float4 of B per k-tile
    int arow[4], acol[4], brow[4], bcol[4];
#pragma unroll
    for (int i = 0; i < 4; i++) {
        int idx = tid + i * 256;
        arow[i] = idx >> 3; acol[i] = (idx & 7) * 4;   // 128 rows x 32 cols
        brow[i] = idx >> 5; bcol[i] = (idx & 31) * 4;  // 32 rows  x 128 cols
    }

    float4 ra[4], rb[4];
#pragma unroll
    for (int i = 0; i < 4; i++) {
        ra[i] = *(const float4*)(A + (size_t)(bm + arow[i]) * K + acol[i]);
        rb[i] = *(const float4*)(B + (size_t)brow[i] * N + bn + bcol[i]);
    }

    float acc[4][4][4];
#pragma unroll
    for (int i = 0; i < 4; i++)
#pragma unroll
        for (int j = 0; j < 4; j++)
#pragma unroll
            for (int e = 0; e < 4; e++) acc[i][j][e] = 0.f;

    const int NT = K / 32;
    int buf = 0;
    for (int t = 0; t < NT; t++) {
        float* Ab = As + buf * AS_STAGE;
        float* Bb = Bs + buf * BS_STAGE;
#pragma unroll
        for (int i = 0; i < 4; i++) {
            *(float4*)&Ab[arow[i] * AS_STRIDE + acol[i]] = cvt4(ra[i]);
            *(float4*)&Bb[brow[i] * BS_STRIDE + bcol[i]] = cvt4(rb[i]);
        }
        __syncthreads();

        if (t + 1 < NT) {
            int k = 32 * (t + 1);
#pragma unroll
            for (int i = 0; i < 4; i++) {
                ra[i] = *(const float4*)(A + (size_t)(bm + arow[i]) * K + k + acol[i]);
                rb[i] = *(const float4*)(B + (size_t)(k + brow[i]) * N + bn + bcol[i]);
            }
        }

#pragma unroll
        for (int kk = 0; kk < 32; kk += 8) {
            uint32_t af[4][4], bf[4][2];
#pragma unroll
            for (int mt = 0; mt < 4; mt++) {
                int r = wm * 64 + mt * 16;
                af[mt][0] = __float_as_uint(Ab[(r + g) * AS_STRIDE + kk + t4]);
                af[mt][1] = __float_as_uint(Ab[(r + g + 8) * AS_STRIDE + kk + t4]);
                af[mt][2] = __float_as_uint(Ab[(r + g) * AS_STRIDE + kk + t4 + 4]);
                af[mt][3] = __float_as_uint(Ab[(r + g + 8) * AS_STRIDE + kk + t4 + 4]);
            }
#pragma unroll
            for (int nt = 0; nt < 4; nt++) {
                int c = wn * 32 + nt * 8 + g;
                bf[nt][0] = __float_as_uint(Bb[(kk + t4) * BS_STRIDE + c]);
                bf[nt][1] = __float_as_uint(Bb[(kk + t4 + 4) * BS_STRIDE + c]);
            }
#pragma unroll
            for (int mt = 0; mt < 4; mt++)
#pragma unroll
                for (int nt = 0; nt < 4; nt++) mma_tf32(acc[mt][nt], af[mt], bf[nt]);
        }
        buf ^= 1;
    }

#pragma unroll
    for (int mt = 0; mt < 4; mt++) {
        int r0 = bm + wm * 64 + mt * 16 + g;
#pragma unroll
        for (int nt = 0; nt < 4; nt++) {
            int c0 = bn + wn * 32 + nt * 8 + 2 * t4;
            *(float2*)&C[(size_t)r0 * N + c0]       = make_float2(acc[mt][nt][0], acc[mt][nt][1]);
            *(float2*)&C[(size_t)(r0 + 8) * N + c0] = make_float2(acc[mt][nt][2], acc[mt][nt][3]);
        }
    }
}

// ---------------- RoPE (in place on q + k heads of g_xqkv) ----------------
__global__ void rope_kernel(const int* __restrict__ seqstarts, const int* __restrict__ start_pos) {
    __shared__ float invf[64];
    int t = blockIdx.x;
    if (threadIdx.x < 64)
        invf[threadIdx.x] = powf(10000.0f, -(float)threadIdx.x / 64.0f);
    __syncthreads();
    int b = 0;
#pragma unroll
    for (int i = 1; i < 4; i++)
        if (t >= seqstarts[i]) b = i;
    float pos = (float)(t - seqstarts[b] + start_pos[b]);
    for (int w = threadIdx.x; w < (NQH + NKVH) * 64; w += blockDim.x) {
        int hh = w >> 6, i = w & 63;
        float ang = pos * invf[i];
        float s, c;
        sincosf(ang, &s, &c);
        float* p = g_xqkv + (size_t)t * QKV_N + hh * HD + 2 * i;
        float x1 = p[0], x2 = p[1];
        p[0] = x1 * c - x2 * s;
        p[1] = x1 * s + x2 * c;
    }
}

// ---------------- gather/merge KV into contiguous [TOTAL_KV, NKVH, HD] ----------------
__global__ void gather_kv(const float* __restrict__ kv_cache,
                          const int* __restrict__ seqstarts, const int* __restrict__ kvstarts,
                          const int* __restrict__ cachestarts, const int* __restrict__ start_pos) {
    int kk = blockIdx.x;
    int h  = blockIdx.y;
    int d  = threadIdx.x;
    int b = 0;
#pragma unroll
    for (int i = 1; i < 4; i++)
        if (kk >= kvstarts[i]) b = i;
    int pkv = kk - kvstarts[b];
    float kvv, vvv;
    if (pkv >= start_pos[b]) {
        int t = seqstarts[b] + pkv - start_pos[b];
        kvv = g_xqkv[(size_t)t * QKV_N + (NQH + h) * HD + d];
        vvv = g_xqkv[(size_t)t * QKV_N + (NQH + NKVH + h) * HD + d];
    } else {
        size_t cidx = (size_t)cachestarts[b] + pkv;
        kvv = kv_cache[(cidx * NKVH + h) * HD + d];
        vvv = kv_cache[(size_t)CACHE_LEN * NKVH * HD + (cidx * NKVH + h) * HD + d];
    }
    g_keys[((size_t)kk * NKVH + h) * HD + d] = kvv;
    g_vals[((size_t)kk * NKVH + h) * HD + d] = vvv;
}

// ---------------- flash attention: BQ=64, KV chunks of 64, tf32 mma ----------------
// grid (16 qtiles, 32 heads), 128 threads (4 warps). Q lives in registers;
// smem = K + V + S stage = 84 KB -> 2 CTAs/SM.
#define ATTN_SMEM ((2 * 64 * 132 + 64 * 65) * 4)

__global__ __launch_bounds__(128, 2) void attn_kernel(const int* __restrict__ seqstarts,
                                                      const int* __restrict__ kvstarts,
                                                      const int* __restrict__ start_pos) {
    extern __shared__ float sm[];
    float* Ks = sm;                 // [64][132]
    float* Vs = sm + 64 * 132;      // [64][132]
    float* Ss = sm + 2 * 64 * 132;  // [64][65]

    const int qtile = blockIdx.x, h = blockIdx.y, kvh = h >> 2;
    const int tid = threadIdx.x, warp = tid >> 5, lane = tid & 31;
    const int g = lane >> 2, t4 = lane & 3;
    const int rb = warp * 16;
    const int qbase = qtile * 64;

    int b = 0;
#pragma unroll
    for (int i = 1; i < 4; i++)
        if (qbase >= seqstarts[i]) b = i;
    const int pos0 = qbase - seqstarts[b] + start_pos[b];
    const int kv_lo = kvstarts[b];
    const int nchunk = (pos0 + 64 + 63) >> 6;

    // stage Q tile through Ks, then fragment into registers (tf32-converted)
    for (int idx = tid; idx < 64 * 32; idx += 128) {
        int r = idx >> 5, c = (idx & 31) << 2;
        *(float4*)&Ks[r * 132 + c] =
            *(const float4*)(g_xqkv + (size_t)(qbase + r) * QKV_N + h * HD + c);
    }
    __syncthreads();
    uint32_t qf[16][4];
#pragma unroll
    for (int ks = 0; ks < 16; ks++) {
        int k0 = ks * 8;
        qf[ks][0] = f2tf(Ks[(rb + g) * 132 + k0 + t4]);
        qf[ks][1] = f2tf(Ks[(rb + g + 8) * 132 + k0 + t4]);
        qf[ks][2] = f2tf(Ks[(rb + g) * 132 + k0 + t4 + 4]);
        qf[ks][3] = f2tf(Ks[(rb + g + 8) * 132 + k0 + t4 + 4]);
    }

    float o[16][4];
#pragma unroll
    for (int nt = 0; nt < 16; nt++)
#pragma unroll
        for (int e = 0; e < 4; e++) o[nt][e] = 0.f;
    float m0 = -1e30f, m1 = -1e30f, l0 = 0.f, l1 = 0.f;
    const float scale = 0.08838834764831845f;  // 1/sqrt(128)

    for (int ch = 0; ch < nchunk; ch++) {
        const int kvb = ch * 64;
        __syncthreads();  // protects Ks/Vs reuse (incl. Q staging on first iter)
        for (int idx = tid; idx < 64 * 32; idx += 128) {
            int r = idx >> 5, c = (idx & 31) << 2;
            size_t go = ((size_t)(kv_lo + kvb + r) * NKVH + kvh) * HD + c;
            *(float4*)&Ks[r * 132 + c] = cvt4(*(const float4*)(g_keys + go));
            *(float4*)&Vs[r * 132 + c] = cvt4(*(const float4*)(g_vals + go));
        }
        __syncthreads();

        // S = Q @ K^T  (warp: 16 rows x 64 kv cols)
        float s[8][4];
#pragma unroll
        for (int nt = 0; nt < 8; nt++)
#pragma unroll
            for (int e = 0; e < 4; e++) s[nt][e] = 0.f;
#pragma unroll
        for (int ks = 0; ks < 16; ks++) {
            int k0 = ks * 8;
#pragma unroll
            for (int nt = 0; nt < 8; nt++) {
                uint32_t bb[2];
                bb[0] = __float_as_uint(Ks[(nt * 8 + g) * 132 + k0 + t4]);
                bb[1] = __float_as_uint(Ks[(nt * 8 + g) * 132 + k0 + t4 + 4]);
                mma_tf32(s[nt], qf[ks], bb);
            }
        }

        // mask + online softmax
        const int plim0 = pos0 + rb + g;
        const int plim1 = plim0 + 8;
        float mx0 = -1e30f, mx1 = -1e30f;
#pragma unroll
        for (int nt = 0; nt < 8; nt++) {
            int c0 = kvb + nt * 8 + 2 * t4;
            float v0 = s[nt][0] * scale; if (c0     > plim0) v0 = -1e30f;
            float v1 = s[nt][1] * scale; if (c0 + 1 > plim0) v1 = -1e30f;
            float v2 = s[nt][2] * scale; if (c0     > plim1) v2 = -1e30f;
            float v3 = s[nt][3] * scale; if (c0 + 1 > plim1) v3 = -1e30f;
            s[nt][0] = v0; s[nt][1] = v1; s[nt][2] = v2; s[nt][3] = v3;
            mx0 = fmaxf(mx0, fmaxf(v0, v1));
            mx1 = fmaxf(mx1, fmaxf(v2, v3));
        }
        mx0 = fmaxf(mx0, __shfl_xor_sync(0xffffffffu, mx0, 1));
        mx0 = fmaxf(mx0, __shfl_xor_sync(0xffffffffu, mx0, 2));
        mx1 = fmaxf(mx1, __shfl_xor_sync(0xffffffffu, mx1, 1));
        mx1 = fmaxf(mx1, __shfl_xor_sync(0xffffffffu, mx1, 2));
        float mn0 = fmaxf(m0, mx0), mn1 = fmaxf(m1, mx1);
        float al0 = __expf(m0 - mn0), al1 = __expf(m1 - mn1);
        float sum0 = 0.f, sum1 = 0.f;
#pragma unroll
        for (int nt = 0; nt < 8; nt++) {
            float p0 = __expf(s[nt][0] - mn0); sum0 += p0;
            float p1 = __expf(s[nt][1] - mn0); sum0 += p1;
            float p2 = __expf(s[nt][2] - mn1); sum1 += p2;
            float p3 = __expf(s[nt][3] - mn1); sum1 += p3;
            int c0 = nt * 8 + 2 * t4;
            Ss[(rb + g) * 65 + c0]         = tfbits(p0);
            Ss[(rb + g) * 65 + c0 + 1]     = tfbits(p1);
            Ss[(rb + g + 8) * 65 + c0]     = tfbits(p2);
            Ss[(rb + g + 8) * 65 + c0 + 1] = tfbits(p3);
        }
        sum0 += __shfl_xor_sync(0xffffffffu, sum0, 1);
        sum0 += __shfl_xor_sync(0xffffffffu, sum0, 2);
        sum1 += __shfl_xor_sync(0xffffffffu, sum1, 1);
        sum1 += __shfl_xor_sync(0xffffffffu, sum1, 2);
        l0 = l0 * al0 + sum0;
        l1 = l1 * al1 + sum1;
        m0 = mn0; m1 = mn1;
#pragma unroll
        for (int nt = 0; nt < 16; nt++) {
            o[nt][0] *= al0; o[nt][1] *= al0;
            o[nt][2] *= al1; o[nt][3] *= al1;
        }
        __syncwarp();

        // O += P @ V
#pragma unroll
        for (int k0 = 0; k0 < 64; k0 += 8) {
            uint32_t a[4];
            a[0] = __float_as_uint(Ss[(rb + g) * 65 + k0 + t4]);
            a[1] = __float_as_uint(Ss[(rb + g + 8) * 65 + k0 + t4]);
            a[2] = __float_as_uint(Ss[(rb + g) * 65 + k0 + t4 + 4]);
            a[3] = __float_as_uint(Ss[(rb + g + 8) * 65 + k0 + t4 + 4]);
#pragma unroll
            for (int nt = 0; nt < 16; nt++) {
                uint32_t bb[2];
                bb[0] = __float_as_uint(Vs[(k0 + t4) * 132 + nt * 8 + g]);
                bb[1] = __float_as_uint(Vs[(k0 + t4 + 4) * 132 + nt * 8 + g]);
                mma_tf32(o[nt], a, bb);
            }
        }
        __syncwarp();
    }

    float il0 = 1.f / l0, il1 = 1.f / l1;
#pragma unroll
    for (int nt = 0; nt < 16; nt++) {
        int r0 = qbase + rb + g;
        int c = h * HD + nt * 8 + 2 * t4;
        *(float2*)&g_attn[(size_t)r0 * HIDDEN + c]       = make_float2(o[nt][0] * il0, o[nt][1] * il0);
        *(float2*)&g_attn[(size_t)(r0 + 8) * HIDDEN + c] = make_float2(o[nt][2] * il1, o[nt][3] * il1);
    }
}

// ---------------- launch ----------------
extern "C" void kernel_launch(void* const* d_in, const int* in_sizes, int n_in,
                              void* d_out, int out_size) {
    const float* x           = (const float*)d_in[0];
    const float* wqkv        = (const float*)d_in[1];
    const float* wo          = (const float*)d_in[2];
    const float* kv_cache    = (const float*)d_in[3];
    const int*   seqstarts   = (const int*)d_in[4];
    const int*   kvstarts    = (const int*)d_in[5];
    const int*   cachestarts = (const int*)d_in[6];
    const int*   start_pos   = (const int*)d_in[7];
    float*       out         = (float*)d_out;

    float *p_xqkv, *p_attn;
    cudaGetSymbolAddress((void**)&p_xqkv, g_xqkv);
    cudaGetSymbolAddress((void**)&p_attn, g_attn);

    static int configured = 0;
    if (!configured) {
        cudaFuncSetAttribute(gemm_tf32, cudaFuncAttributeMaxDynamicSharedMemorySize, GEMM_SMEM);
        cudaFuncSetAttribute(attn_kernel, cudaFuncAttributeMaxDynamicSharedMemorySize, ATTN_SMEM);
        configured = 1;
    }

    // 1) xqkv = x @ wqkv
    gemm_tf32<<<dim3(QKV_N / 128, TOK / 128), 256, GEMM_SMEM>>>(x, wqkv, p_xqkv, TOK, QKV_N, HIDDEN);
    // 2) RoPE on q,k
    rope_kernel<<<TOK, 256>>>(seqstarts, start_pos);
    // 3) merge new k/v with cache
    gather_kv<<<dim3(TOTAL_KV, NKVH), 128>>>(kv_cache, seqstarts, kvstarts, cachestarts, start_pos);
    // 4) flash attention
    attn_kernel<<<dim3(TOK / 64, NQH), 128, ATTN_SMEM>>>(seqstarts, kvstarts, start_pos);
    // 5) out = attn @ wo
    gemm_tf32<<<dim3(HIDDEN / 128, TOK / 128), 256, GEMM_SMEM>>>(p_attn, wo, out, TOK, HIDDEN, HIDDEN);
}

// round 4
// speedup vs baseline: 2.4667x; 2.0846x over previous
#include <cuda_runtime.h>
#include <cuda_fp16.h>
#include <cstdint>

#define TOK      1024
#define HIDDEN   4096
#define NQH      32
#define NKVH     8
#define HD       128
#define QKV_N    6144
#define TOTAL_KV 3072
#define CACHE_LEN 8192

// ---------------- scratch (static device globals; allocation-free) ----------------
__device__ __half g_xh[TOK * HIDDEN];
__device__ __half g_w1h[HIDDEN * QKV_N];
__device__ __half g_w2h[HIDDEN * HIDDEN];
__device__ float  g_xqkv[TOK * QKV_N];
__device__ __half g_qh[TOK * HIDDEN];
__device__ __half g_keysh[TOTAL_KV * NKVH * HD];
__device__ __half g_valsh[TOTAL_KV * NKVH * HD];
__device__ __half g_attnh[TOK * HIDDEN];

// ---------------- helpers ----------------
__device__ __forceinline__ uint32_t smem_u32(const void* p) {
    uint32_t a;
    asm("{ .reg .u64 t; cvta.to.shared.u64 t, %1; cvt.u32.u64 %0, t; }" : "=r"(a) : "l"(p));
    return a;
}

// D += A(16x8) * B(8x8) over k=16, fp16 in / fp32 acc
__device__ __forceinline__ void mma_f16(float* d, const uint32_t* a, const uint32_t* b) {
    asm volatile(
        "mma.sync.aligned.m16n8k16.row.col.f32.f16.f16.f32 "
        "{%0,%1,%2,%3}, {%4,%5,%6,%7}, {%8,%9}, {%0,%1,%2,%3};\n"
        : "+f"(d[0]), "+f"(d[1]), "+f"(d[2]), "+f"(d[3])
        : "r"(a[0]), "r"(a[1]), "r"(a[2]), "r"(a[3]), "r"(b[0]), "r"(b[1]));
}

#define LDSM_X4(r0, r1, r2, r3, addr) \
    asm volatile("ldmatrix.sync.aligned.m8n8.x4.shared.b16 {%0,%1,%2,%3}, [%4];" \
                 : "=r"(r0), "=r"(r1), "=r"(r2), "=r"(r3) : "r"(addr))
#define LDSM_X2T(r0, r1, addr) \
    asm volatile("ldmatrix.sync.aligned.m8n8.x2.trans.shared.b16 {%0,%1}, [%2];" \
                 : "=r"(r0), "=r"(r1) : "r"(addr))

// ---------------- fp32 -> fp16 conversion ----------------
__global__ void conv_f2h(const float4* __restrict__ in, __half2* __restrict__ out, int n4) {
    int i = blockIdx.x * blockDim.x + threadIdx.x;
    if (i < n4) {
        float4 v = in[i];
        out[2 * i]     = __floats2half2_rn(v.x, v.y);
        out[2 * i + 1] = __floats2half2_rn(v.z, v.w);
    }
}

// ---------------- fp16 GEMM: C[M,N](f32) = A[M,K](h) @ B[K,N](h) ----------------
// BM=128, BN=128, BK=32. 256 threads = 8 warps (2m x 4n), warp tile 64x32.
// Double-buffered static smem, one sync per tile. ldmatrix frags.
#define A_STR 40        // halfs per As row (32 + 8 pad)
#define B_STR 136       // halfs per Bs row (128 + 8 pad)
#define A_STAGE_B (128 * A_STR * 2)   // 10240 bytes
#define B_STAGE_B (32 * B_STR * 2)    // 8704 bytes

__global__ __launch_bounds__(256, 2) void gemm_f16(const __half* __restrict__ A,
                                                   const __half* __restrict__ B,
                                                   float* __restrict__ C,
                                                   int M, int N, int K) {
    __shared__ __align__(16) __half As[2][128 * A_STR];
    __shared__ __align__(16) __half Bs[2][32 * B_STR];

    const int tid = threadIdx.x, warp = tid >> 5, lane = tid & 31;
    const int wm = warp >> 2, wn = warp & 3;
    const int g = lane >> 2, t4 = lane & 3;
    const int bm = blockIdx.y * 128, bn = blockIdx.x * 128;

    // staging slots (2 iters each)
    int ar[2], ac[2], bkr[2], bnc[2];
#pragma unroll
    for (int it = 0; it < 2; it++) {
        int idx = tid + it * 256;
        ar[it] = idx >> 2;  ac[it]  = (idx & 3) * 8;    // A: 128 rows x 32 halfs
        bkr[it] = idx >> 4; bnc[it] = (idx & 15) * 8;   // B: 32 rows x 128 halfs
    }

    uint4 pa[2], pb[2];
#pragma unroll
    for (int it = 0; it < 2; it++) {
        pa[it] = *(const uint4*)(A + (size_t)(bm + ar[it]) * K + ac[it]);
        pb[it] = *(const uint4*)(B + (size_t)bkr[it] * N + bn + bnc[it]);
    }

    // ldmatrix per-lane address components
    const uint32_t sA0 = smem_u32(As), sB0 = smem_u32(Bs);
    const int aRow = (lane & 7) + ((lane >> 3) & 1) * 8;   // 0..15
    const int aCol = ((lane >> 4) & 1) * 8;                // 0 or 8
    const int bRow = lane & 15;                            // 0..15

    float acc[4][4][4];
#pragma unroll
    for (int i = 0; i < 4; i++)
#pragma unroll
        for (int j = 0; j < 4; j++)
#pragma unroll
            for (int e = 0; e < 4; e++) acc[i][j][e] = 0.f;

    const int NT = K / 32;
    for (int t = 0; t < NT; t++) {
        const int buf = t & 1;
#pragma unroll
        for (int it = 0; it < 2; it++) {
            *(uint4*)(&As[buf][ar[it] * A_STR + ac[it]]) = pa[it];
            *(uint4*)(&Bs[buf][bkr[it] * B_STR + bnc[it]]) = pb[it];
        }
        __syncthreads();

        if (t + 1 < NT) {
            int k0 = (t + 1) * 32;
#pragma unroll
            for (int it = 0; it < 2; it++) {
                pa[it] = *(const uint4*)(A + (size_t)(bm + ar[it]) * K + k0 + ac[it]);
                pb[it] = *(const uint4*)(B + (size_t)(k0 + bkr[it]) * N + bn + bnc[it]);
            }
        }

        const uint32_t sAb = sA0 + buf * A_STAGE_B;
        const uint32_t sBb = sB0 + buf * B_STAGE_B;
#pragma unroll
        for (int kk = 0; kk < 32; kk += 16) {
            uint32_t af[4][4], bf[4][2];
#pragma unroll
            for (int mt = 0; mt < 4; mt++) {
                uint32_t addr = sAb + ((wm * 64 + mt * 16 + aRow) * A_STR + kk + aCol) * 2;
                LDSM_X4(af[mt][0], af[mt][1], af[mt][2], af[mt][3], addr);
            }
#pragma unroll
            for (int nt = 0; nt < 4; nt++) {
                uint32_t addr = sBb + ((kk + bRow) * B_STR + wn * 32 + nt * 8) * 2;
                LDSM_X2T(bf[nt][0], bf[nt][1], addr);
            }
#pragma unroll
            for (int mt = 0; mt < 4; mt++)
#pragma unroll
                for (int nt = 0; nt < 4; nt++) mma_f16(acc[mt][nt], af[mt], bf[nt]);
        }
    }

#pragma unroll
    for (int mt = 0; mt < 4; mt++) {
        int r0 = bm + wm * 64 + mt * 16 + g;
#pragma unroll
        for (int nt = 0; nt < 4; nt++) {
            int c0 = bn + wn * 32 + nt * 8 + 2 * t4;
            *(float2*)&C[(size_t)r0 * N + c0]       = make_float2(acc[mt][nt][0], acc[mt][nt][1]);
            *(float2*)&C[(size_t)(r0 + 8) * N + c0] = make_float2(acc[mt][nt][2], acc[mt][nt][3]);
        }
    }
}

// ---------------- RoPE: q-heads -> g_qh (half), k-heads in-place fp32 ----------------
__global__ void rope_kernel(const int* __restrict__ seqstarts, const int* __restrict__ start_pos) {
    __shared__ float invf[64];
    int t = blockIdx.x;
    if (threadIdx.x < 64)
        invf[threadIdx.x] = powf(10000.0f, -(float)threadIdx.x / 64.0f);
    __syncthreads();
    int b = 0;
#pragma unroll
    for (int i = 1; i < 4; i++)
        if (t >= seqstarts[i]) b = i;
    float pos = (float)(t - seqstarts[b] + start_pos[b]);
    for (int w = threadIdx.x; w < (NQH + NKVH) * 64; w += blockDim.x) {
        int hh = w >> 6, i = w & 63;
        float ang = pos * invf[i];
        float s, c;
        sincosf(ang, &s, &c);
        float* p = g_xqkv + (size_t)t * QKV_N + hh * HD + 2 * i;
        float x1 = p[0], x2 = p[1];
        float r1 = x1 * c - x2 * s;
        float r2 = x1 * s + x2 * c;
        if (hh < NQH) {
            ((__half2*)g_qh)[(size_t)t * (HIDDEN / 2) + hh * 64 + i] = __floats2half2_rn(r1, r2);
        } else {
            p[0] = r1; p[1] = r2;
        }
    }
}

// ---------------- gather/merge KV (half output) ----------------
__global__ void gather_kv(const float* __restrict__ kv_cache,
                          const int* __restrict__ seqstarts, const int* __restrict__ kvstarts,
                          const int* __restrict__ cachestarts, const int* __restrict__ start_pos) {
    int kk = blockIdx.x;
    int h  = blockIdx.y;
    int d  = threadIdx.x;
    int b = 0;
#pragma unroll
    for (int i = 1; i < 4; i++)
        if (kk >= kvstarts[i]) b = i;
    int pkv = kk - kvstarts[b];
    float kvv, vvv;
    if (pkv >= start_pos[b]) {
        int t = seqstarts[b] + pkv - start_pos[b];
        kvv = g_xqkv[(size_t)t * QKV_N + (NQH + h) * HD + d];
        vvv = g_xqkv[(size_t)t * QKV_N + (NQH + NKVH + h) * HD + d];
    } else {
        size_t cidx = (size_t)cachestarts[b] + pkv;
        kvv = kv_cache[(cidx * NKVH + h) * HD + d];
        vvv = kv_cache[(size_t)CACHE_LEN * NKVH * HD + (cidx * NKVH + h) * HD + d];
    }
    g_keysh[((size_t)kk * NKVH + h) * HD + d] = __float2half_rn(kvv);
    g_valsh[((size_t)kk * NKVH + h) * HD + d] = __float2half_rn(vvv);
}

// ---------------- flash attention fp16: BQ=64, KV chunks of 64 ----------------
// 128 threads (4 warps x 16 q rows). Q frags from gmem; P register-resident.
#define KV_STR 136   // halfs per K/V smem row

__global__ __launch_bounds__(128, 3) void attn_kernel(const int* __restrict__ seqstarts,
                                                      const int* __restrict__ kvstarts,
                                                      const int* __restrict__ start_pos) {
    __shared__ __align__(16) __half Ks[64 * KV_STR];
    __shared__ __align__(16) __half Vs[64 * KV_STR];

    const int qtile = blockIdx.x, h = blockIdx.y, kvh = h >> 2;
    const int tid = threadIdx.x, warp = tid >> 5, lane = tid & 31;
    const int g = lane >> 2, t4 = lane & 3;
    const int rb = warp * 16;
    const int qbase = qtile * 64;

    int b = 0;
#pragma unroll
    for (int i = 1; i < 4; i++)
        if (qbase >= seqstarts[i]) b = i;
    const int pos0 = qbase - seqstarts[b] + start_pos[b];
    const int kv_lo = kvstarts[b];
    const int nchunk = (pos0 + 64 + 63) >> 6;

    // Q fragments direct from gmem (half)
    uint32_t qf[8][4];
    {
        const uint32_t* q0 = (const uint32_t*)(g_qh + (size_t)(qbase + rb + g) * HIDDEN + h * HD);
        const uint32_t* q1 = (const uint32_t*)(g_qh + (size_t)(qbase + rb + g + 8) * HIDDEN + h * HD);
#pragma unroll
        for (int f = 0; f < 8; f++) {
            qf[f][0] = q0[f * 8 + t4];
            qf[f][1] = q1[f * 8 + t4];
            qf[f][2] = q0[f * 8 + t4 + 4];
            qf[f][3] = q1[f * 8 + t4 + 4];
        }
    }

    const uint32_t* Ks32 = (const uint32_t*)Ks;
    const uint32_t sV = smem_u32(Vs);
    const int vRow = lane & 15;

    float o[16][4];
#pragma unroll
    for (int nt = 0; nt < 16; nt++)
#pragma unroll
        for (int e = 0; e < 4; e++) o[nt][e] = 0.f;
    float m0 = -1e30f, m1 = -1e30f, l0 = 0.f, l1 = 0.f;
    const float scale = 0.08838834764831845f;

    for (int ch = 0; ch < nchunk; ch++) {
        const int kvb = ch * 64;
        __syncthreads();
#pragma unroll
        for (int it = 0; it < 8; it++) {
            int idx = tid + it * 128;
            int r = idx >> 4, c = (idx & 15) * 8;
            size_t go = (size_t)(kv_lo + kvb + r) * (NKVH * HD) + kvh * HD + c;
            *(uint4*)(&Ks[r * KV_STR + c]) = *(const uint4*)(g_keysh + go);
            *(uint4*)(&Vs[r * KV_STR + c]) = *(const uint4*)(g_valsh + go);
        }
        __syncthreads();

        // S = Q @ K^T  (16 rows x 64 kv), k frames of 16
        float s[8][4];
#pragma unroll
        for (int nt = 0; nt < 8; nt++)
#pragma unroll
            for (int e = 0; e < 4; e++) s[nt][e] = 0.f;
#pragma unroll
        for (int f = 0; f < 8; f++) {
#pragma unroll
            for (int nt = 0; nt < 8; nt++) {
                uint32_t bb[2];
                bb[0] = Ks32[(nt * 8 + g) * (KV_STR / 2) + f * 8 + t4];
                bb[1] = Ks32[(nt * 8 + g) * (KV_STR / 2) + f * 8 + t4 + 4];
                mma_f16(s[nt], qf[f], bb);
            }
        }

        // mask + online softmax (fp32)
        const int plim0 = pos0 + rb + g;
        const int plim1 = plim0 + 8;
        float mx0 = -1e30f, mx1 = -1e30f;
#pragma unroll
        for (int nt = 0; nt < 8; nt++) {
            int c0 = kvb + nt * 8 + 2 * t4;
            float v0 = s[nt][0] * scale; if (c0     > plim0) v0 = -1e30f;
            float v1 = s[nt][1] * scale; if (c0 + 1 > plim0) v1 = -1e30f;
            float v2 = s[nt][2] * scale; if (c0     > plim1) v2 = -1e30f;
            float v3 = s[nt][3] * scale; if (c0 + 1 > plim1) v3 = -1e30f;
            s[nt][0] = v0; s[nt][1] = v1; s[nt][2] = v2; s[nt][3] = v3;
            mx0 = fmaxf(mx0, fmaxf(v0, v1));
            mx1 = fmaxf(mx1, fmaxf(v2, v3));
        }
        mx0 = fmaxf(mx0, __shfl_xor_sync(0xffffffffu, mx0, 1));
        mx0 = fmaxf(mx0, __shfl_xor_sync(0xffffffffu, mx0, 2));
        mx1 = fmaxf(mx1, __shfl_xor_sync(0xffffffffu, mx1, 1));
        mx1 = fmaxf(mx1, __shfl_xor_sync(0xffffffffu, mx1, 2));
        float mn0 = fmaxf(m0, mx0), mn1 = fmaxf(m1, mx1);
        float al0 = __expf(m0 - mn0), al1 = __expf(m1 - mn1);
        float sum0 = 0.f, sum1 = 0.f;
#pragma unroll
        for (int nt = 0; nt < 8; nt++) {
            s[nt][0] = __expf(s[nt][0] - mn0); sum0 += s[nt][0];
            s[nt][1] = __expf(s[nt][1] - mn0); sum0 += s[nt][1];
            s[nt][2] = __expf(s[nt][2] - mn1); sum1 += s[nt][2];
            s[nt][3] = __expf(s[nt][3] - mn1); sum1 += s[nt][3];
        }
        sum0 += __shfl_xor_sync(0xffffffffu, sum0, 1);
        sum0 += __shfl_xor_sync(0xffffffffu, sum0, 2);
        sum1 += __shfl_xor_sync(0xffffffffu, sum1, 1);
        sum1 += __shfl_xor_sync(0xffffffffu, sum1, 2);
        l0 = l0 * al0 + sum0;
        l1 = l1 * al1 + sum1;
        m0 = mn0; m1 = mn1;
#pragma unroll
        for (int nt = 0; nt < 16; nt++) {
            o[nt][0] *= al0; o[nt][1] *= al0;
            o[nt][2] *= al1; o[nt][3] *= al1;
        }

        // P fragments: pack fp32 probs -> half2 (register-resident, no smem)
        uint32_t pa[4][4];
#pragma unroll
        for (int kf = 0; kf < 4; kf++) {
            __half2 h0 = __floats2half2_rn(s[2 * kf][0], s[2 * kf][1]);
            __half2 h1 = __floats2half2_rn(s[2 * kf][2], s[2 * kf][3]);
            __half2 h2 = __floats2half2_rn(s[2 * kf + 1][0], s[2 * kf + 1][1]);
            __half2 h3 = __floats2half2_rn(s[2 * kf + 1][2], s[2 * kf + 1][3]);
            pa[kf][0] = *(uint32_t*)&h0;
            pa[kf][1] = *(uint32_t*)&h1;
            pa[kf][2] = *(uint32_t*)&h2;
            pa[kf][3] = *(uint32_t*)&h3;
        }

        // O += P @ V : V frags via ldmatrix.x2.trans from Vs[kv][d]
#pragma unroll
        for (int kf = 0; kf < 4; kf++) {
            uint32_t vbase = sV + ((kf * 16 + vRow) * KV_STR) * 2;
#pragma unroll
            for (int nt = 0; nt < 16; nt++) {
                uint32_t bb[2];
                LDSM_X2T(bb[0], bb[1], vbase + nt * 16);
                mma_f16(o[nt], pa[kf], bb);
            }
        }
    }

    float il0 = 1.f / l0, il1 = 1.f / l1;
    __half2* out2 = (__half2*)g_attnh;
#pragma unroll
    for (int nt = 0; nt < 16; nt++) {
        size_t r0 = qbase + rb + g;
        int c2 = h * (HD / 2) + nt * 4 + t4;
        out2[r0 * (HIDDEN / 2) + c2]       = __floats2half2_rn(o[nt][0] * il0, o[nt][1] * il0);
        out2[(r0 + 8) * (HIDDEN / 2) + c2] = __floats2half2_rn(o[nt][2] * il1, o[nt][3] * il1);
    }
}

// ---------------- launch ----------------
extern "C" void kernel_launch(void* const* d_in, const int* in_sizes, int n_in,
                              void* d_out, int out_size) {
    const float* x           = (const float*)d_in[0];
    const float* wqkv        = (const float*)d_in[1];
    const float* wo          = (const float*)d_in[2];
    const float* kv_cache    = (const float*)d_in[3];
    const int*   seqstarts   = (const int*)d_in[4];
    const int*   kvstarts    = (const int*)d_in[5];
    const int*   cachestarts = (const int*)d_in[6];
    const int*   start_pos   = (const int*)d_in[7];
    float*       out         = (float*)d_out;

    __half *p_xh, *p_w1h, *p_w2h, *p_attnh;
    float* p_xqkv;
    cudaGetSymbolAddress((void**)&p_xh, g_xh);
    cudaGetSymbolAddress((void**)&p_w1h, g_w1h);
    cudaGetSymbolAddress((void**)&p_w2h, g_w2h);
    cudaGetSymbolAddress((void**)&p_attnh, g_attnh);
    cudaGetSymbolAddress((void**)&p_xqkv, g_xqkv);

    // 0) fp32 -> fp16 conversions
    conv_f2h<<<(TOK * HIDDEN / 4 + 255) / 256, 256>>>((const float4*)x, (__half2*)p_xh, TOK * HIDDEN / 4);
    conv_f2h<<<(HIDDEN * QKV_N / 4 + 255) / 256, 256>>>((const float4*)wqkv, (__half2*)p_w1h, HIDDEN * QKV_N / 4);
    conv_f2h<<<(HIDDEN * HIDDEN / 4 + 255) / 256, 256>>>((const float4*)wo, (__half2*)p_w2h, HIDDEN * HIDDEN / 4);

    // 1) xqkv = x @ wqkv (fp32 out)
    gemm_f16<<<dim3(QKV_N / 128, TOK / 128), 256>>>(p_xh, p_w1h, p_xqkv, TOK, QKV_N, HIDDEN);
    // 2) RoPE: q -> g_qh (half), k in-place fp32
    rope_kernel<<<TOK, 256>>>(seqstarts, start_pos);
    // 3) merge new k/v with cache -> half
    gather_kv<<<dim3(TOTAL_KV, NKVH), 128>>>(kv_cache, seqstarts, kvstarts, cachestarts, start_pos);
    // 4) flash attention -> g_attnh (half)
    attn_kernel<<<dim3(TOK / 64, NQH), 128>>>(seqstarts, kvstarts, start_pos);
    // 5) out = attn @ wo (fp32 out)
    gemm_f16<<<dim3(HIDDEN / 128, TOK / 128), 256>>>(p_attnh, p_w2h, out, TOK, HIDDEN, HIDDEN);
}